// round 3
// baseline (speedup 1.0000x reference)
#include <cuda_runtime.h>
#include <cuda_bf16.h>
#include <cstdint>

typedef __nv_bfloat16 bf16;

#define B_ 32
#define T_ 512
#define E_ 512
#define H_ 1024
#define O_ 128
#define G_ 4096
#define NCTA 128

// ---------------- scratch (static device globals; no allocs) ----------------
__device__ __align__(16) bf16  g_e[B_ * T_ * E_];          // gathered embeddings (bf16)
__device__ __align__(16) bf16  g_Wih[G_ * E_];             // W_ih bf16
__device__ __align__(16) bf16  g_Wp[NCTA * 32 * H_];       // W_hh packed per-CTA
__device__ __align__(16) bf16  g_Wo[O_ * H_];              // W_lin[:,H:2H]
__device__ __align__(16) bf16  g_Wv[O_ * H_];              // W_lin[:,0:H]
__device__ __align__(16) float g_xp[(size_t)T_ * B_ * G_]; // x_proj fp32 [T][B][4H]
__device__ __align__(16) bf16  g_hs[(size_t)B_ * T_ * H_]; // hidden states [B][T][H]
__device__ __align__(16) bf16  g_hbuf[2][B_ * H_];         // h double buffer
__device__ float g_vc[B_ * O_];                            // verb logits (+ b_lin)
__device__ int   g_cnt;
__device__ int   g_epoch;

// ---------------- PTX helpers ----------------
__device__ __forceinline__ uint32_t smem_u32(const void* p) {
    return (uint32_t)__cvta_generic_to_shared(p);
}
__device__ __forceinline__ void ldm_x4(uint32_t* r, uint32_t a) {
    asm volatile("ldmatrix.sync.aligned.m8n8.x4.shared.b16 {%0,%1,%2,%3}, [%4];"
                 : "=r"(r[0]), "=r"(r[1]), "=r"(r[2]), "=r"(r[3]) : "r"(a));
}
__device__ __forceinline__ void ldm_x2(uint32_t* r, uint32_t a) {
    asm volatile("ldmatrix.sync.aligned.m8n8.x2.shared.b16 {%0,%1}, [%2];"
                 : "=r"(r[0]), "=r"(r[1]) : "r"(a));
}
__device__ __forceinline__ void mma16816(float* d, const uint32_t* a, const uint32_t* b) {
    asm volatile(
        "mma.sync.aligned.m16n8k16.row.col.f32.bf16.bf16.f32 "
        "{%0,%1,%2,%3}, {%4,%5,%6,%7}, {%8,%9}, {%0,%1,%2,%3};\n"
        : "+f"(d[0]), "+f"(d[1]), "+f"(d[2]), "+f"(d[3])
        : "r"(a[0]), "r"(a[1]), "r"(a[2]), "r"(a[3]), "r"(b[0]), "r"(b[1]));
}
__device__ __forceinline__ float sigmoidf_(float x) { return 1.f / (1.f + __expf(-x)); }

// ---------------- prep kernels ----------------
__global__ void k_gather(const int* __restrict__ tok, const float* __restrict__ emb) {
    int i = blockIdx.x * 256 + threadIdx.x;   // B*T*E/4 quads
    int m = i >> 7;                           // 128 quads per row
    int q = i & 127;
    int t = tok[m];
    float4 v = *(const float4*)(emb + (size_t)t * E_ + q * 4);
    __nv_bfloat162* d2 = (__nv_bfloat162*)(g_e + (size_t)m * E_ + q * 4);
    d2[0] = __floats2bfloat162_rn(v.x, v.y);
    d2[1] = __floats2bfloat162_rn(v.z, v.w);
}

__global__ void k_convert(const float* __restrict__ s, bf16* __restrict__ d, int n4) {
    int i = blockIdx.x * 256 + threadIdx.x;
    if (i >= n4) return;
    float4 v = ((const float4*)s)[i];
    ((__nv_bfloat162*)d)[2 * i]     = __floats2bfloat162_rn(v.x, v.y);
    ((__nv_bfloat162*)d)[2 * i + 1] = __floats2bfloat162_rn(v.z, v.w);
}

__global__ void k_split(const float* __restrict__ wl) {
    int i = blockIdx.x * 256 + threadIdx.x;   // O*2H
    if (i >= O_ * 2 * H_) return;
    int o = i >> 11;
    int k = i & 2047;
    bf16 v = __float2bfloat16(wl[i]);
    if (k < H_) g_Wv[o * H_ + k] = v;
    else        g_Wo[o * H_ + (k - H_)] = v;
}

__global__ void k_pack(const float* __restrict__ whh) {
    int i = blockIdx.x * 256 + threadIdx.x;   // NCTA*32*H
    int k = i & (H_ - 1);
    int r = (i >> 10) & 31;
    int c = i >> 15;
    int row = (r >> 3) * H_ + c * 8 + (r & 7);
    g_Wp[i] = __float2bfloat16(whh[(size_t)row * H_ + k]);
}

__global__ void k_init() {
    int i = blockIdx.x * 256 + threadIdx.x;
    if (i == 0) { g_cnt = 0; g_epoch = 0; }
    if (i < 2 * B_ * H_) ((bf16*)g_hbuf)[i] = __float2bfloat16(0.0f);
}

// -------- generic bf16 NT mma GEMM: C[M,N] = A[M,K]*B[N,K]^T (+bias) --------
// BM=64 BN=64 BK=32, 128 threads (2x2 warps, 32x32 warp tile)
__global__ void __launch_bounds__(128) k_gemm(
    const bf16* __restrict__ A, const bf16* __restrict__ Bm, float* __restrict__ C,
    int M, int N, int K,
    const float* __restrict__ bias1, const float* __restrict__ bias2, int remap)
{
    __shared__ __align__(16) bf16 As[64 * 40];
    __shared__ __align__(16) bf16 Bs[64 * 40];
    const int tid = threadIdx.x, lane = tid & 31, w = tid >> 5;
    const int bm = blockIdx.x * 64, bn = blockIdx.y * 64;
    const int wm = (w & 1) * 32, wn = (w >> 1) * 32;

    float acc[2][4][4];
#pragma unroll
    for (int i = 0; i < 2; i++)
#pragma unroll
        for (int j = 0; j < 4; j++)
#pragma unroll
            for (int r = 0; r < 4; r++) acc[i][j][r] = 0.f;

    for (int k0 = 0; k0 < K; k0 += 32) {
#pragma unroll
        for (int c = tid; c < 256; c += 128) {
            int r = c >> 2, q = c & 3;
            *(uint4*)&As[r * 40 + q * 8] = *(const uint4*)(A + (size_t)(bm + r) * K + k0 + q * 8);
            *(uint4*)&Bs[r * 40 + q * 8] = *(const uint4*)(Bm + (size_t)(bn + r) * K + k0 + q * 8);
        }
        __syncthreads();
#pragma unroll
        for (int kk = 0; kk < 32; kk += 16) {
            uint32_t af[2][4], bfr[4][2];
#pragma unroll
            for (int i = 0; i < 2; i++)
                ldm_x4(af[i], smem_u32(&As[(wm + i * 16 + (lane & 15)) * 40 + kk + (lane >> 4) * 8]));
#pragma unroll
            for (int j = 0; j < 2; j++) {
                int row = wn + j * 16 + (lane & 7) + ((lane >> 4) << 3);
                int col = kk + ((lane >> 3) & 1) * 8;
                uint32_t r4[4];
                ldm_x4(r4, smem_u32(&Bs[row * 40 + col]));
                bfr[j * 2][0] = r4[0]; bfr[j * 2][1] = r4[1];
                bfr[j * 2 + 1][0] = r4[2]; bfr[j * 2 + 1][1] = r4[3];
            }
#pragma unroll
            for (int i = 0; i < 2; i++)
#pragma unroll
                for (int j = 0; j < 4; j++) mma16816(acc[i][j], af[i], bfr[j]);
        }
        __syncthreads();
    }
#pragma unroll
    for (int i = 0; i < 2; i++)
#pragma unroll
        for (int j = 0; j < 4; j++) {
            int cN = bn + wn + j * 8 + (lane & 3) * 2;
            float bc0 = (bias1 ? bias1[cN] : 0.f) + (bias2 ? bias2[cN] : 0.f);
            float bc1 = (bias1 ? bias1[cN + 1] : 0.f) + (bias2 ? bias2[cN + 1] : 0.f);
#pragma unroll
            for (int p = 0; p < 2; p++) {
                int rr = bm + wm + i * 16 + (lane >> 2) + p * 8;
                int dst = remap ? ((rr & (T_ - 1)) * B_ + (rr >> 9)) : rr;
                C[(size_t)dst * N + cN]     = acc[i][j][2 * p + 0] + bc0;
                C[(size_t)dst * N + cN + 1] = acc[i][j][2 * p + 1] + bc1;
            }
        }
}

// ---------------- persistent recurrent LSTM kernel ----------------
// 128 CTAs x 256 threads (8 warps). CTA c owns h cols [8c,8c+8) and gate rows
// {g*H + 8c..8c+8}. smem: Ws[32][1032] + As[32][1032] bf16 + gates[32][33] f32.
#define SMEM_LSTM (66048 * 2 + 4224)

__global__ void __launch_bounds__(256, 1) k_lstm() {
    extern __shared__ char smemraw[];
    bf16*  Ws    = (bf16*)smemraw;
    bf16*  As    = (bf16*)(smemraw + 66048);
    float* gates = (float*)(smemraw + 2 * 66048);
    const int tid = threadIdx.x, lane = tid & 31, w = tid >> 5;
    const int cta = blockIdx.x;
    const int wm = (w >> 2) * 16, wn = (w & 3) * 8;

    // W slice (32 rows x 1024) -> smem, stride 1032
    for (int i = tid; i < 4096; i += 256) {
        int r = i >> 7, q = i & 127;
        *(uint4*)&Ws[r * 1032 + q * 8] = *(const uint4*)(g_Wp + ((size_t)cta * 32 + r) * H_ + q * 8);
    }
    __syncthreads();

    const int b_i = tid >> 3, jl = tid & 7;
    const int gcol = cta * 8 + jl;
    float creg = 0.f;

    for (int t = 0; t < T_; t++) {
        const bf16* hsrc = g_hbuf[t & 1];
        // load full h [32,1024] into smem (bypass L1 for cross-CTA coherence)
        for (int i = tid; i < 4096; i += 256) {
            int r = i >> 7, q = i & 127;
            uint4 v = __ldcg((const uint4*)(hsrc + (size_t)r * H_ + q * 8));
            *(uint4*)&As[r * 1032 + q * 8] = v;
        }
        __syncthreads();

        float acc[4][4];
#pragma unroll
        for (int a = 0; a < 4; a++)
#pragma unroll
            for (int r = 0; r < 4; r++) acc[a][r] = 0.f;
#pragma unroll 16
        for (int kk = 0; kk < H_; kk += 16) {
            uint32_t af[4], bf2[2];
            ldm_x4(af, smem_u32(&As[(wm + (lane & 15)) * 1032 + kk + (lane >> 4) * 8]));
            ldm_x2(bf2, smem_u32(&Ws[(wn + (lane & 7)) * 1032 + kk + ((lane >> 3) & 1) * 8]));
            mma16816(acc[(kk >> 4) & 3], af, bf2);
        }
        float s0 = acc[0][0] + acc[1][0] + acc[2][0] + acc[3][0];
        float s1 = acc[0][1] + acc[1][1] + acc[2][1] + acc[3][1];
        float s2 = acc[0][2] + acc[1][2] + acc[2][2] + acc[3][2];
        float s3 = acc[0][3] + acc[1][3] + acc[2][3] + acc[3][3];
        int gr = wm + (lane >> 2), gc = wn + (lane & 3) * 2;
        gates[gr * 33 + gc]           = s0;
        gates[gr * 33 + gc + 1]       = s1;
        gates[(gr + 8) * 33 + gc]     = s2;
        gates[(gr + 8) * 33 + gc + 1] = s3;
        __syncthreads();

        // elementwise cell update for (batch b_i, column gcol)
        const float* xrow = g_xp + (size_t)(t * B_ + b_i) * G_;
        float pi = gates[b_i * 33 + jl]       + xrow[gcol];
        float pf = gates[b_i * 33 + 8 + jl]   + xrow[H_ + gcol];
        float pg = gates[b_i * 33 + 16 + jl]  + xrow[2 * H_ + gcol];
        float po = gates[b_i * 33 + 24 + jl]  + xrow[3 * H_ + gcol];
        float ig = sigmoidf_(pi), fg = sigmoidf_(pf), og = sigmoidf_(po);
        float gg = tanhf(pg);
        creg = fg * creg + ig * gg;
        float h = og * tanhf(creg);
        bf16 hb = __float2bfloat16(h);
        g_hbuf[(t + 1) & 1][b_i * H_ + gcol] = hb;
        g_hs[((size_t)b_i * T_ + t) * H_ + gcol] = hb;

        // grid barrier (epoch counting)
        __threadfence();
        __syncthreads();
        if (tid == 0) {
            int old = atomicAdd(&g_cnt, 1);
            if (old == NCTA - 1) {
                g_cnt = 0;
                __threadfence();
                atomicAdd(&g_epoch, 1);
            } else {
                while (*(volatile int*)&g_epoch < t + 1) __nanosleep(64);
            }
        }
        __syncthreads();
    }
}

// -------- verb logits: vc[b][o] = dot(hs[b,vidx[b],:], Wv[o,:]) + b_lin[o] --------
__global__ void k_vc(const int* __restrict__ vidx, const float* __restrict__ blin) {
    __shared__ bf16 vrow[H_];
    int b = blockIdx.x, tid = threadIdx.x;
    int t = vidx[b];
    for (int i = tid; i < H_; i += 128) vrow[i] = g_hs[((size_t)b * T_ + t) * H_ + i];
    __syncthreads();
    float s = 0.f;
    const bf16* wr = g_Wv + (size_t)tid * H_;
    for (int k = 0; k < H_; k += 2) {
        __nv_bfloat162 wv = *(const __nv_bfloat162*)(wr + k);
        __nv_bfloat162 hv = *(const __nv_bfloat162*)(vrow + k);
        s += __bfloat162float(wv.x) * __bfloat162float(hv.x)
           + __bfloat162float(wv.y) * __bfloat162float(hv.y);
    }
    g_vc[b * O_ + tid] = s + blin[tid];
}

// -------- fused add-verb-logits + log_softmax over O=128 --------
__global__ void k_lsm(float* __restrict__ out) {
    int m = blockIdx.x, tid = threadIdx.x, w = tid >> 5;
    int b = m >> 9;
    float x = out[(size_t)m * O_ + tid] + g_vc[b * O_ + tid];
    float mx = x;
#pragma unroll
    for (int o = 16; o; o >>= 1) mx = fmaxf(mx, __shfl_xor_sync(0xffffffffu, mx, o));
    __shared__ float s1[4], s2[4];
    if ((tid & 31) == 0) s1[w] = mx;
    __syncthreads();
    mx = fmaxf(fmaxf(s1[0], s1[1]), fmaxf(s1[2], s1[3]));
    float e = __expf(x - mx);
    float sm = e;
#pragma unroll
    for (int o = 16; o; o >>= 1) sm += __shfl_xor_sync(0xffffffffu, sm, o);
    if ((tid & 31) == 0) s2[w] = sm;
    __syncthreads();
    sm = s2[0] + s2[1] + s2[2] + s2[3];
    out[(size_t)m * O_ + tid] = x - mx - __logf(sm);
}

extern "C" void kernel_launch(void* const* d_in, const int* in_sizes, int n_in,
                              void* d_out, int out_size) {
    const int*   tokens = (const int*)d_in[0];
    const int*   vidx   = (const int*)d_in[1];
    const float* emb    = (const float*)d_in[2];
    const float* W_ih   = (const float*)d_in[3];
    const float* W_hh   = (const float*)d_in[4];
    const float* b_ih   = (const float*)d_in[5];
    const float* b_hh   = (const float*)d_in[6];
    const float* W_lin  = (const float*)d_in[7];
    const float* b_lin  = (const float*)d_in[8];
    float* out = (float*)d_out;

    static int smem_set = 0;
    if (!smem_set) {
        cudaFuncSetAttribute(k_lstm, cudaFuncAttributeMaxDynamicSharedMemorySize, SMEM_LSTM);
        smem_set = 1;
    }

    k_init<<<256, 256>>>();
    k_gather<<<(B_ * T_ * E_ / 4) / 256, 256>>>(tokens, emb);
    k_convert<<<(G_ * E_ / 4 + 255) / 256, 256>>>(W_ih, g_Wih, G_ * E_ / 4);
    k_pack<<<(NCTA * 32 * H_) / 256, 256>>>(W_hh);
    k_split<<<(O_ * 2 * H_) / 256, 256>>>(W_lin);

    {   // x_proj: [16384,4096] = e @ W_ih^T + b_ih + b_hh, remapped to [T][B][4H]
        bf16* eptr; cudaGetSymbolAddress((void**)&eptr, g_e);
        dim3 grid(16384 / 64, 4096 / 64);
        k_gemm<<<grid, 128>>>(g_e, g_Wih, g_xp, 16384, 4096, 512, b_ih, b_hh, 1);
    }

    k_lstm<<<NCTA, 256, SMEM_LSTM>>>();

    {   // out-part logits: [16384,128] = hs @ Wo^T  (written straight to d_out)
        dim3 grid(16384 / 64, 128 / 64);
        k_gemm<<<grid, 128>>>(g_hs, g_Wo, out, 16384, 128, 1024, nullptr, nullptr, 0);
    }
    k_vc<<<B_, 128>>>(vidx, b_lin);
    k_lsm<<<B_ * T_, 128>>>(out);
}